// round 15
// baseline (speedup 1.0000x reference)
#include <cuda_runtime.h>
#include <cuda_bf16.h>

#define INPUT_DIM 4
#define H1 64
#define H2 32
#define BATCH 64
#define SEQ 4096

#define NT_L2 128           // tids 0..127   (low wid)
#define NT_L1 128           // tids 128..255 (high wid -> arbiter priority)
#define NTHREADS (NT_L1 + NT_L2)
#define RING 4              // slot s <-> named barrier id 2+s (joint, count 256)

typedef unsigned long long ull;

// ---- packed f32x2 helpers ----
__device__ __forceinline__ ull pk2(float a, float b) {
    ull r; asm("mov.b64 %0, {%1, %2};" : "=l"(r) : "f"(a), "f"(b)); return r;
}
__device__ __forceinline__ void upk2(ull v, float& a, float& b) {
    asm("mov.b64 {%0, %1}, %2;" : "=f"(a), "=f"(b) : "l"(v));
}
__device__ __forceinline__ ull fma2(ull a, ull b, ull c) {
    ull d; asm("fma.rn.f32x2 %0, %1, %2, %3;" : "=l"(d) : "l"(a), "l"(b), "l"(c)); return d;
}
__device__ __forceinline__ ull add2(ull a, ull b) {
    ull d; asm("add.rn.f32x2 %0, %1, %2;" : "=l"(d) : "l"(a), "l"(b)); return d;
}
__device__ __forceinline__ float tanh_approx(float x) {
    float y; asm("tanh.approx.f32 %0, %1;" : "=f"(y) : "f"(x)); return y;
}
__device__ __forceinline__ void bar_sync(int id, int cnt) {
    asm volatile("bar.sync %0, %1;" :: "r"(id), "r"(cnt) : "memory");
}

__global__ void __launch_bounds__(NTHREADS, 1)
lstm2_kernel(const float* __restrict__ x,
             const float* __restrict__ W_ih1, const float* __restrict__ W_hh1,
             const float* __restrict__ b_ih1, const float* __restrict__ b_hh1,
             const float* __restrict__ W_ih2, const float* __restrict__ W_hh2,
             const float* __restrict__ b_ih2, const float* __restrict__ b_hh2,
             float* __restrict__ out)
{
    const int b   = blockIdx.x;
    const int tid = threadIdx.x;

    __shared__ __align__(16) float h1ring[RING][H1];
    __shared__ __align__(16) float h2buf[2][H2];

    const bool isL1 = tid >= NT_L2;   // L1 in HIGH tids -> arbiter priority

    if (isL1 && ((tid - NT_L2) & 1)) h1ring[RING - 1][(tid - NT_L2) >> 1] = 0.0f; // h1(-1)=0
    if (!isL1 && ((tid & 3) == 0)) h2buf[0][tid >> 2] = 0.0f;                     // h2(-1)=0
    __syncthreads();

    if (isL1) {
        // ======== Layer 1 (critical path): 2 gates per thread ========
        const int l   = tid - NT_L2;
        const int u   = l >> 1;
        const int par = l & 1;
        const int rowA = par * H1 + u;        // par0: i, par1: f
        const int rowB = (2 + par) * H1 + u;  // par0: g, par1: o

        const float bS = par ? 0.5f : 1.0f;   // gateB: g->tanh, o->sigmoid
        const float bA = par ? 0.5f : 1.0f;
        const float bB = par ? 0.5f : 0.0f;

        ull wA[32], wB[32], xA0, xA1, xB0, xB1;
        {
            const float2* whhA = reinterpret_cast<const float2*>(W_hh1 + rowA * H1);
            const float2* whhB = reinterpret_cast<const float2*>(W_hh1 + rowB * H1);
            #pragma unroll
            for (int k = 0; k < 32; ++k) {
                float2 v = whhA[k]; wA[k] = pk2(v.x, v.y);
                float2 w = whhB[k]; wB[k] = pk2(w.x, w.y);
            }
            const float2* wihA = reinterpret_cast<const float2*>(W_ih1 + rowA * INPUT_DIM);
            const float2* wihB = reinterpret_cast<const float2*>(W_ih1 + rowB * INPUT_DIM);
            float2 v;
            v = wihA[0]; xA0 = pk2(v.x, v.y);
            v = wihA[1]; xA1 = pk2(v.x, v.y);
            v = wihB[0]; xB0 = pk2(v.x, v.y);
            v = wihB[1]; xB1 = pk2(v.x, v.y);
        }
        const ull biasAp = pk2(b_ih1[rowA] + b_hh1[rowA], 0.0f);
        const ull biasBp = pk2(b_ih1[rowB] + b_hh1[rowB], 0.0f);

        const float4* xb4 = reinterpret_cast<const float4*>(x + (size_t)b * SEQ * INPUT_DIM);
        float c = 0.0f;            // valid in par==1 lanes
        float4 xv  = __ldg(xb4);                       // x(0)
        float4 xv1 = __ldg(xb4 + (SEQ > 1 ? 1 : 0));   // x(1)

        #pragma unroll 1
        for (int t = 0; t < SEQ; ++t) {
            const int tn2 = (t + 2 < SEQ) ? (t + 2) : (SEQ - 1);
            const float4 xv2 = __ldg(xb4 + tn2);       // depth-2 prefetch

            const ulonglong2* hv =
                reinterpret_cast<const ulonglong2*>(h1ring[(t + RING - 1) & (RING - 1)]);
            const ull xp0 = pk2(xv.x, xv.y);
            const ull xp1 = pk2(xv.z, xv.w);

            // x-part at chain head (off the LDS-dependent tail)
            ull a0 = fma2(xA0, xp0, biasAp), a1 = fma2(xA1, xp1, 0ull);
            ull d0 = fma2(xB0, xp0, biasBp), d1 = fma2(xB1, xp1, 0ull);
            ull a2 = 0ull, a3 = 0ull, d2 = 0ull, d3 = 0ull;
            #pragma unroll
            for (int kk = 0; kk < 8; ++kk) {
                const ulonglong2 hA = hv[2 * kk];
                const ulonglong2 hB = hv[2 * kk + 1];
                a0 = fma2(wA[4 * kk + 0], hA.x, a0);
                d0 = fma2(wB[4 * kk + 0], hA.x, d0);
                a1 = fma2(wA[4 * kk + 1], hA.y, a1);
                d1 = fma2(wB[4 * kk + 1], hA.y, d1);
                a2 = fma2(wA[4 * kk + 2], hB.x, a2);
                d2 = fma2(wB[4 * kk + 2], hB.x, d2);
                a3 = fma2(wA[4 * kk + 3], hB.y, a3);
                d3 = fma2(wB[4 * kk + 3], hB.y, d3);
            }
            a0 = add2(add2(a0, a1), add2(a2, a3));
            d0 = add2(add2(d0, d1), add2(d2, d3));
            float alo, ahi, dlo, dhi;
            upk2(a0, alo, ahi); upk2(d0, dlo, dhi);
            const float rawA = alo + ahi;
            const float rawB = dlo + dhi;

            const float sA = __fmaf_rn(0.5f, tanh_approx(0.5f * rawA), 0.5f); // sigmoid
            const float sB = __fmaf_rn(bA, tanh_approx(bS * rawB), bB);

            const float val = sA * sB;                          // par0: i*g
            const float ig  = __shfl_xor_sync(0xffffffffu, val, 1);
            const float fc  = sA * c;                           // par1: f*c (overlaps shfl)
            c = fc + ig;                                        // par1: c = f*c + i*g
            const float h = sB * tanh_approx(c);                // par1: h = o*tanh(c)
            if (par) h1ring[t & (RING - 1)][u] = h;

            bar_sync(2 + (t & (RING - 1)), NTHREADS);   // joint slot barrier
            xv = xv1; xv1 = xv2;
        }
    } else {
        // ======== Layer 2 (low wids): 1 gate per thread, skewed one extra slot ========
        // iteration t: arrive joint bar(t) FIRST, then compute step t-1.
        // Final step SEQ-1 drains after the loop (L1 finished; slots frozen).
        const int u = tid >> 2;
        const int q = tid & 3;
        const float actS = (q == 2) ? 1.0f : 0.5f;
        const float actA = (q == 2) ? 1.0f : 0.5f;
        const float actB = (q == 2) ? 0.0f : 0.5f;

        const int g = q * H2 + u;
        ull w2[48];
        {
            const float2* wih = reinterpret_cast<const float2*>(W_ih2 + g * H1);
            #pragma unroll
            for (int k = 0; k < 32; ++k) { const float2 v = wih[k]; w2[k] = pk2(v.x, v.y); }
            const float2* whh = reinterpret_cast<const float2*>(W_hh2 + g * H2);
            #pragma unroll
            for (int k = 0; k < 16; ++k) { const float2 v = whh[k]; w2[32 + k] = pk2(v.x, v.y); }
        }
        const ull biasp = pk2(b_ih2[g] + b_hh2[g], 0.0f);
        float* outb = out + (size_t)b * SEQ * H2;

        float c = 0.0f;

        #pragma unroll 1
        for (int t = 0; t < SEQ; ++t) {
            bar_sync(2 + (t & (RING - 1)), NTHREADS);   // join L1's step-t barrier
            if (t < 1) continue;                        // skew: nothing to do yet
            const int s = t - 1;                        // compute step s

            const ulonglong2* hv = reinterpret_cast<const ulonglong2*>(h1ring[s & (RING - 1)]);
            const ulonglong2* gv = reinterpret_cast<const ulonglong2*>(h2buf[s & 1]);

            ull a0 = biasp, a1 = 0ull, a2 = 0ull, a3 = 0ull;
            #pragma unroll
            for (int kk = 0; kk < 8; ++kk) {
                const ulonglong2 hA = hv[2 * kk];
                const ulonglong2 hB = hv[2 * kk + 1];
                a0 = fma2(w2[4 * kk + 0], hA.x, a0);
                a1 = fma2(w2[4 * kk + 1], hA.y, a1);
                a2 = fma2(w2[4 * kk + 2], hB.x, a2);
                a3 = fma2(w2[4 * kk + 3], hB.y, a3);
            }
            #pragma unroll
            for (int kk = 0; kk < 4; ++kk) {
                const ulonglong2 hA = gv[2 * kk];
                const ulonglong2 hB = gv[2 * kk + 1];
                a0 = fma2(w2[32 + 4 * kk + 0], hA.x, a0);
                a1 = fma2(w2[32 + 4 * kk + 1], hA.y, a1);
                a2 = fma2(w2[32 + 4 * kk + 2], hB.x, a2);
                a3 = fma2(w2[32 + 4 * kk + 3], hB.y, a3);
            }
            a0 = add2(add2(a0, a1), add2(a2, a3));
            float lo, hi; upk2(a0, lo, hi);
            const float raw = lo + hi;

            const float act = __fmaf_rn(actA, tanh_approx(actS * raw), actB);
            const float v1 = __shfl_xor_sync(0xffffffffu, act, 1);
            const float v2 = __shfl_xor_sync(0xffffffffu, act, 2);
            const float v3 = __shfl_xor_sync(0xffffffffu, act, 3);
            c = __fmaf_rn(v1, c, act * v2);
            const float h = v3 * tanh_approx(c);

            if (q == 0) {
                h2buf[(s + 1) & 1][u] = h;   // ordered vs step s+1 by next joint bar
                outb[(size_t)s * H2 + u] = h;
            }
        }

        // ---- drain final step SEQ-1 (no more joint bars; L2-private ordering) ----
        bar_sync(7, NT_L2);   // order h2buf[(SEQ-1)&1] writes vs reads below
        {
            const int s = SEQ - 1;
            const ulonglong2* hv = reinterpret_cast<const ulonglong2*>(h1ring[s & (RING - 1)]);
            const ulonglong2* gv = reinterpret_cast<const ulonglong2*>(h2buf[s & 1]);

            ull a0 = biasp, a1 = 0ull, a2 = 0ull, a3 = 0ull;
            #pragma unroll
            for (int kk = 0; kk < 8; ++kk) {
                const ulonglong2 hA = hv[2 * kk];
                const ulonglong2 hB = hv[2 * kk + 1];
                a0 = fma2(w2[4 * kk + 0], hA.x, a0);
                a1 = fma2(w2[4 * kk + 1], hA.y, a1);
                a2 = fma2(w2[4 * kk + 2], hB.x, a2);
                a3 = fma2(w2[4 * kk + 3], hB.y, a3);
            }
            #pragma unroll
            for (int kk = 0; kk < 4; ++kk) {
                const ulonglong2 hA = gv[2 * kk];
                const ulonglong2 hB = gv[2 * kk + 1];
                a0 = fma2(w2[32 + 4 * kk + 0], hA.x, a0);
                a1 = fma2(w2[32 + 4 * kk + 1], hA.y, a1);
                a2 = fma2(w2[32 + 4 * kk + 2], hB.x, a2);
                a3 = fma2(w2[32 + 4 * kk + 3], hB.y, a3);
            }
            a0 = add2(add2(a0, a1), add2(a2, a3));
            float lo, hi; upk2(a0, lo, hi);
            const float raw = lo + hi;

            const float act = __fmaf_rn(actA, tanh_approx(actS * raw), actB);
            const float v1 = __shfl_xor_sync(0xffffffffu, act, 1);
            const float v2 = __shfl_xor_sync(0xffffffffu, act, 2);
            const float v3 = __shfl_xor_sync(0xffffffffu, act, 3);
            c = __fmaf_rn(v1, c, act * v2);
            const float h = v3 * tanh_approx(c);

            if (q == 0) outb[(size_t)s * H2 + u] = h;
        }
    }
}

extern "C" void kernel_launch(void* const* d_in, const int* in_sizes, int n_in,
                              void* d_out, int out_size) {
    const float* x     = (const float*)d_in[0];
    const float* W_ih1 = (const float*)d_in[1];
    const float* W_hh1 = (const float*)d_in[2];
    const float* b_ih1 = (const float*)d_in[3];
    const float* b_hh1 = (const float*)d_in[4];
    const float* W_ih2 = (const float*)d_in[5];
    const float* W_hh2 = (const float*)d_in[6];
    const float* b_ih2 = (const float*)d_in[7];
    const float* b_hh2 = (const float*)d_in[8];
    float* out = (float*)d_out;

    lstm2_kernel<<<BATCH, NTHREADS>>>(x, W_ih1, W_hh1, b_ih1, b_hh1,
                                      W_ih2, W_hh2, b_ih2, b_hh2, out);
}

// round 16
// speedup vs baseline: 1.1119x; 1.1119x over previous
#include <cuda_runtime.h>
#include <cuda_bf16.h>

#define INPUT_DIM 4
#define H1 64
#define H2 32
#define BATCH 64
#define SEQ 4096

#define NT_L2 128           // tids 0..127   (low wid)
#define NT_L1 128           // tids 128..255 (high wid -> arbiter priority)
#define NTHREADS (NT_L1 + NT_L2)
#define RING 4              // slot s <-> named barrier id 2+s (joint, count 256)

typedef unsigned long long ull;

// ---- packed f32x2 helpers ----
__device__ __forceinline__ ull pk2(float a, float b) {
    ull r; asm("mov.b64 %0, {%1, %2};" : "=l"(r) : "f"(a), "f"(b)); return r;
}
__device__ __forceinline__ void upk2(ull v, float& a, float& b) {
    asm("mov.b64 {%0, %1}, %2;" : "=f"(a), "=f"(b) : "l"(v));
}
__device__ __forceinline__ ull fma2(ull a, ull b, ull c) {
    ull d; asm("fma.rn.f32x2 %0, %1, %2, %3;" : "=l"(d) : "l"(a), "l"(b), "l"(c)); return d;
}
__device__ __forceinline__ ull add2(ull a, ull b) {
    ull d; asm("add.rn.f32x2 %0, %1, %2;" : "=l"(d) : "l"(a), "l"(b)); return d;
}
__device__ __forceinline__ float tanh_approx(float x) {
    float y; asm("tanh.approx.f32 %0, %1;" : "=f"(y) : "f"(x)); return y;
}
__device__ __forceinline__ void bar_sync(int id, int cnt) {
    asm volatile("bar.sync %0, %1;" :: "r"(id), "r"(cnt) : "memory");
}

__global__ void __launch_bounds__(NTHREADS, 1)
lstm2_kernel(const float* __restrict__ x,
             const float* __restrict__ W_ih1, const float* __restrict__ W_hh1,
             const float* __restrict__ b_ih1, const float* __restrict__ b_hh1,
             const float* __restrict__ W_ih2, const float* __restrict__ W_hh2,
             const float* __restrict__ b_ih2, const float* __restrict__ b_hh2,
             float* __restrict__ out)
{
    const int b   = blockIdx.x;
    const int tid = threadIdx.x;

    __shared__ __align__(16) float h1ring[RING][H1];
    __shared__ __align__(16) float h2buf[2][H2];

    const bool isL1 = tid >= NT_L2;   // L1 in HIGH tids -> arbiter priority

    if (isL1 && ((tid - NT_L2) & 1)) h1ring[RING - 1][(tid - NT_L2) >> 1] = 0.0f; // h1(-1)=0
    if (!isL1 && ((tid & 3) == 0)) h2buf[0][tid >> 2] = 0.0f;                     // h2(-1)=0
    __syncthreads();

    if (isL1) {
        // ======== Layer 1 (critical path): 2 gates per thread ========
        const int l   = tid - NT_L2;
        const int u   = l >> 1;
        const int par = l & 1;
        const int rowA = par * H1 + u;        // par0: i, par1: f   (both sigmoid)
        const int rowB = (2 + par) * H1 + u;  // par0: g (tanh), par1: o (sigmoid)

        // sigmoid(x) = 0.5*tanh(0.5x)+0.5 -> fold the 0.5x into the weights
        const float scA = 0.5f;                    // gateA always sigmoid
        const float scB = par ? 0.5f : 1.0f;       // g: 1.0, o: 0.5
        const float bA  = par ? 0.5f : 1.0f;       // act = bA*tanh(raw) + bB
        const float bB  = par ? 0.5f : 0.0f;

        ull wA[32], wB[32], xA0, xA1, xB0, xB1;
        {
            const float2* whhA = reinterpret_cast<const float2*>(W_hh1 + rowA * H1);
            const float2* whhB = reinterpret_cast<const float2*>(W_hh1 + rowB * H1);
            #pragma unroll
            for (int k = 0; k < 32; ++k) {
                float2 v = whhA[k]; wA[k] = pk2(scA * v.x, scA * v.y);
                float2 w = whhB[k]; wB[k] = pk2(scB * w.x, scB * w.y);
            }
            const float2* wihA = reinterpret_cast<const float2*>(W_ih1 + rowA * INPUT_DIM);
            const float2* wihB = reinterpret_cast<const float2*>(W_ih1 + rowB * INPUT_DIM);
            float2 v;
            v = wihA[0]; xA0 = pk2(scA * v.x, scA * v.y);
            v = wihA[1]; xA1 = pk2(scA * v.x, scA * v.y);
            v = wihB[0]; xB0 = pk2(scB * v.x, scB * v.y);
            v = wihB[1]; xB1 = pk2(scB * v.x, scB * v.y);
        }
        const ull biasAp = pk2(scA * (b_ih1[rowA] + b_hh1[rowA]), 0.0f);
        const ull biasBp = pk2(scB * (b_ih1[rowB] + b_hh1[rowB]), 0.0f);

        const float4* xb4 = reinterpret_cast<const float4*>(x + (size_t)b * SEQ * INPUT_DIM);
        float c = 0.0f;            // valid in par==1 lanes
        float4 xv  = __ldg(xb4);                       // x(0)
        float4 xv1 = __ldg(xb4 + (SEQ > 1 ? 1 : 0));   // x(1)

        #pragma unroll 1
        for (int t = 0; t < SEQ; ++t) {
            const int tn2 = (t + 2 < SEQ) ? (t + 2) : (SEQ - 1);
            const float4 xv2 = __ldg(xb4 + tn2);       // depth-2 prefetch

            const ulonglong2* hv =
                reinterpret_cast<const ulonglong2*>(h1ring[(t + RING - 1) & (RING - 1)]);
            const ull xp0 = pk2(xv.x, xv.y);
            const ull xp1 = pk2(xv.z, xv.w);

            // x-part at chain head (off the LDS-dependent tail)
            ull a0 = fma2(xA0, xp0, biasAp), a1 = fma2(xA1, xp1, 0ull);
            ull d0 = fma2(xB0, xp0, biasBp), d1 = fma2(xB1, xp1, 0ull);
            ull a2 = 0ull, a3 = 0ull, d2 = 0ull, d3 = 0ull;
            #pragma unroll
            for (int kk = 0; kk < 8; ++kk) {
                const ulonglong2 hA = hv[2 * kk];
                const ulonglong2 hB = hv[2 * kk + 1];
                a0 = fma2(wA[4 * kk + 0], hA.x, a0);
                d0 = fma2(wB[4 * kk + 0], hA.x, d0);
                a1 = fma2(wA[4 * kk + 1], hA.y, a1);
                d1 = fma2(wB[4 * kk + 1], hA.y, d1);
                a2 = fma2(wA[4 * kk + 2], hB.x, a2);
                d2 = fma2(wB[4 * kk + 2], hB.x, d2);
                a3 = fma2(wA[4 * kk + 3], hB.y, a3);
                d3 = fma2(wB[4 * kk + 3], hB.y, d3);
            }
            a0 = add2(add2(a0, a1), add2(a2, a3));
            d0 = add2(add2(d0, d1), add2(d2, d3));
            float alo, ahi, dlo, dhi;
            upk2(a0, alo, ahi); upk2(d0, dlo, dhi);
            const float rawA = alo + ahi;   // already pre-scaled for sigmoid
            const float rawB = dlo + dhi;

            const float sA = __fmaf_rn(0.5f, tanh_approx(rawA), 0.5f);  // sigmoid
            const float sB = __fmaf_rn(bA, tanh_approx(rawB), bB);      // g: tanh, o: sigmoid

            const float val = sA * sB;                          // par0: i*g
            const float ig  = __shfl_xor_sync(0xffffffffu, val, 1);
            const float fc  = sA * c;                           // par1: f*c (overlaps shfl)
            c = fc + ig;                                        // par1: c = f*c + i*g
            const float h = sB * tanh_approx(c);                // par1: h = o*tanh(c)
            if (par) h1ring[t & (RING - 1)][u] = h;

            bar_sync(2 + (t & (RING - 1)), NTHREADS);   // joint slot barrier
            xv = xv1; xv1 = xv2;
        }
    } else {
        // ======== Layer 2 (low wids): 1 gate per thread ========
        const int u = tid >> 2;
        const int q = tid & 3;
        const float sc   = (q == 2) ? 1.0f : 0.5f;   // prescale for sigmoid gates
        const float actA = (q == 2) ? 1.0f : 0.5f;
        const float actB = (q == 2) ? 0.0f : 0.5f;

        const int g = q * H2 + u;
        ull w2[48];
        {
            const float2* wih = reinterpret_cast<const float2*>(W_ih2 + g * H1);
            #pragma unroll
            for (int k = 0; k < 32; ++k) {
                const float2 v = wih[k]; w2[k] = pk2(sc * v.x, sc * v.y);
            }
            const float2* whh = reinterpret_cast<const float2*>(W_hh2 + g * H2);
            #pragma unroll
            for (int k = 0; k < 16; ++k) {
                const float2 v = whh[k]; w2[32 + k] = pk2(sc * v.x, sc * v.y);
            }
        }
        const ull biasp = pk2(sc * (b_ih2[g] + b_hh2[g]), 0.0f);
        float* outb = out + (size_t)b * SEQ * H2;

        float c = 0.0f;

        #pragma unroll 1
        for (int t = 0; t < SEQ; ++t) {
            // joint slot barrier: h1(t) visible after this; also orders our
            // h2buf writes from step t-1 against this step's reads.
            bar_sync(2 + (t & (RING - 1)), NTHREADS);

            const ulonglong2* hv = reinterpret_cast<const ulonglong2*>(h1ring[t & (RING - 1)]);
            const ulonglong2* gv = reinterpret_cast<const ulonglong2*>(h2buf[t & 1]);

            ull a0 = biasp, a1 = 0ull, a2 = 0ull, a3 = 0ull;
            #pragma unroll
            for (int kk = 0; kk < 8; ++kk) {
                const ulonglong2 hA = hv[2 * kk];
                const ulonglong2 hB = hv[2 * kk + 1];
                a0 = fma2(w2[4 * kk + 0], hA.x, a0);
                a1 = fma2(w2[4 * kk + 1], hA.y, a1);
                a2 = fma2(w2[4 * kk + 2], hB.x, a2);
                a3 = fma2(w2[4 * kk + 3], hB.y, a3);
            }
            #pragma unroll
            for (int kk = 0; kk < 4; ++kk) {
                const ulonglong2 hA = gv[2 * kk];
                const ulonglong2 hB = gv[2 * kk + 1];
                a0 = fma2(w2[32 + 4 * kk + 0], hA.x, a0);
                a1 = fma2(w2[32 + 4 * kk + 1], hA.y, a1);
                a2 = fma2(w2[32 + 4 * kk + 2], hB.x, a2);
                a3 = fma2(w2[32 + 4 * kk + 3], hB.y, a3);
            }
            a0 = add2(add2(a0, a1), add2(a2, a3));
            float lo, hi; upk2(a0, lo, hi);
            const float raw = lo + hi;   // pre-scaled

            const float act = __fmaf_rn(actA, tanh_approx(raw), actB);
            const float v1 = __shfl_xor_sync(0xffffffffu, act, 1);
            const float v2 = __shfl_xor_sync(0xffffffffu, act, 2);
            const float v3 = __shfl_xor_sync(0xffffffffu, act, 3);
            const float fc = v1 * c;            // overlaps the v2/v3 shuffles
            c = fc + act * v2;
            const float h = v3 * tanh_approx(c);

            if (q == 0) {
                h2buf[(t + 1) & 1][u] = h;
                outb[(size_t)t * H2 + u] = h;
            }
        }
    }
}

extern "C" void kernel_launch(void* const* d_in, const int* in_sizes, int n_in,
                              void* d_out, int out_size) {
    const float* x     = (const float*)d_in[0];
    const float* W_ih1 = (const float*)d_in[1];
    const float* W_hh1 = (const float*)d_in[2];
    const float* b_ih1 = (const float*)d_in[3];
    const float* b_hh1 = (const float*)d_in[4];
    const float* W_ih2 = (const float*)d_in[5];
    const float* W_hh2 = (const float*)d_in[6];
    const float* b_ih2 = (const float*)d_in[7];
    const float* b_hh2 = (const float*)d_in[8];
    float* out = (float*)d_out;

    lstm2_kernel<<<BATCH, NTHREADS>>>(x, W_ih1, W_hh1, b_ih1, b_hh1,
                                      W_ih2, W_hh2, b_ih2, b_hh2, out);
}